// round 5
// baseline (speedup 1.0000x reference)
#include <cuda_runtime.h>
#include <cstdint>

// Problem constants: B*C = 16, L = 128, N = 48
#define BC 16

// Scratch (device globals; allocation in kernel_launch is forbidden)
__device__ float g_bufA[(size_t)BC * 16384 * 48];
__device__ float g_bufB[(size_t)BC * 6144  * 48];
__device__ float g_bufC[(size_t)BC * 2304  * 48];

// Precomputed W fragments (mma B-operand layout), hi/lo tf32 split.
__device__ float2 g_wfHi[6][3072];
__device__ float2 g_wfLo[6][3072];

__device__ __forceinline__ float tf32r(float v) {
    uint32_t r; asm("cvt.rna.tf32.f32 %0, %1;" : "=r"(r) : "f"(v));
    return __uint_as_float(r);
}

__device__ __forceinline__ void mma_tf32(float d[4], const float4& a, const float2& b) {
    asm volatile(
        "mma.sync.aligned.m16n8k8.row.col.f32.tf32.tf32.f32 "
        "{%0,%1,%2,%3}, {%4,%5,%6,%7}, {%8,%9}, {%0,%1,%2,%3};"
        : "+f"(d[0]), "+f"(d[1]), "+f"(d[2]), "+f"(d[3])
        : "r"(__float_as_uint(a.x)), "r"(__float_as_uint(a.y)),
          "r"(__float_as_uint(a.z)), "r"(__float_as_uint(a.w)),
          "r"(__float_as_uint(b.x)), "r"(__float_as_uint(b.y)));
}

// Build mma-B-fragment layout for all 6 weight matrices (hi/lo tf32 split).
__global__ void prep_wfrag(const float* __restrict__ W0, const float* __restrict__ W1,
                           const float* __restrict__ W2, const float* __restrict__ W3,
                           const float* __restrict__ W4, const float* __restrict__ W5)
{
    const int m = blockIdx.y;
    const float* W = (m==0)?W0:(m==1)?W1:(m==2)?W2:(m==3)?W3:(m==4)?W4:W5;
    const int M   = (m < 3) ? 48 : 128;
    const int NMT = M / 8;
    const int t = blockIdx.x * blockDim.x + threadIdx.x;   // 0..3071
    const int rem  = t % (NMT * 32);
    const int kc   = t / (NMT * 32);
    const int mt   = rem / 32;
    const int lane = rem % 32;
    const int tq = lane & 3, gid = lane >> 2;
    const float v0 = W[(kc*8 + tq)     * M + mt*8 + gid];
    const float v1 = W[(kc*8 + tq + 4) * M + mt*8 + gid];
    const float h0 = tf32r(v0), h1 = tf32r(v1);
    g_wfHi[m][t] = make_float2(h0, h1);
    g_wfLo[m][t] = make_float2(tf32r(v0 - h0), tf32r(v1 - h1));
}

// out[b][j][m] = sum_k in[b][k][j] * W[k][m]   (3xTF32, m16n8k8)
// Warp grid: MWARPS m-warps x JW j-groups; each warp: NSL strips x NTILE m-tiles.
// A panel staged once in smem in fragment-ready layout (one LDS.128 = one frag).
// PRESPLIT=false: smem holds fp32, hi/lo split in regs at use (encode — smem is
// the occupancy binder there). PRESPLIT=true: smem holds hi/lo (decode — all
// m-warps reread every fragment; avoid redundant cvt).
// kc-outer loop: B fragments live in regs, reused across NSL strips.
template<int K, int M, int NW, int NS, int MWARPS, int NTILE, bool PRESPLIT, int MINB>
__global__ void __launch_bounds__(NW * 32, MINB) mma_stage(
    const float* __restrict__ in, const float2* __restrict__ wHi,
    const float2* __restrict__ wLo, float* __restrict__ out, int J)
{
    constexpr int KC  = K / 8;
    constexpr int NMT = M / 8;
    constexpr int BJ  = NS * 16;
    constexpr int JW  = NW / MWARPS;
    constexpr int NSL = NS / JW;

    __shared__ float4 As[(PRESPLIT ? 2 : 1) * KC * NS * 32];

    const int tid  = threadIdx.x;
    const int lane = tid & 31, warp = tid >> 5;
    const int tq = lane & 3, gid = lane >> 2;
    const int b  = blockIdx.z;
    const int j0 = blockIdx.x * BJ;
    const int mt0 = (warp % MWARPS) * NTILE;
    const int s0  = (warp / MWARPS) * NSL;

    // ---- stage A panel (lane-owns-slot fragment layout) ----
    const float* inb = in + (size_t)b * K * J + j0;
#pragma unroll
    for (int t = warp; t < KC * NS; t += NW) {
        const int kcb = t / NS, s = t % NS;
        const float* p = inb + (size_t)(kcb * 8 + tq) * J + s * 16 + gid;
        float4 v = make_float4(p[0], p[8], p[(size_t)4 * J], p[(size_t)4 * J + 8]);
        if (PRESPLIT) {
            float4 h = make_float4(tf32r(v.x), tf32r(v.y), tf32r(v.z), tf32r(v.w));
            float4 l = make_float4(tf32r(v.x - h.x), tf32r(v.y - h.y),
                                   tf32r(v.z - h.z), tf32r(v.w - h.w));
            As[t * 32 + lane] = h;
            As[KC * NS * 32 + t * 32 + lane] = l;
        } else {
            As[t * 32 + lane] = v;
        }
    }
    __syncthreads();

    float acc[NSL][NTILE][4];
#pragma unroll
    for (int sl = 0; sl < NSL; sl++)
#pragma unroll
        for (int nt = 0; nt < NTILE; nt++)
#pragma unroll
            for (int r = 0; r < 4; r++) acc[sl][nt][r] = 0.0f;

#pragma unroll 2
    for (int kc = 0; kc < KC; kc++) {
        float2 bh[NTILE], bl[NTILE];
#pragma unroll
        for (int nt = 0; nt < NTILE; nt++) {
            bh[nt] = __ldg(&wHi[(kc * NMT + mt0 + nt) * 32 + lane]);
            bl[nt] = __ldg(&wLo[(kc * NMT + mt0 + nt) * 32 + lane]);
        }
#pragma unroll
        for (int sl = 0; sl < NSL; sl++) {
            float4 ah, al;
            if (PRESPLIT) {
                ah = As[(kc * NS + s0 + sl) * 32 + lane];
                al = As[KC * NS * 32 + (kc * NS + s0 + sl) * 32 + lane];
            } else {
                float4 v = As[(kc * NS + s0 + sl) * 32 + lane];
                ah = make_float4(tf32r(v.x), tf32r(v.y), tf32r(v.z), tf32r(v.w));
                al = make_float4(tf32r(v.x - ah.x), tf32r(v.y - ah.y),
                                 tf32r(v.z - ah.z), tf32r(v.w - ah.w));
            }
#pragma unroll
            for (int nt = 0; nt < NTILE; nt++) {
                mma_tf32(acc[sl][nt], al, bh[nt]);   // small cross terms first
                mma_tf32(acc[sl][nt], ah, bl[nt]);
                mma_tf32(acc[sl][nt], ah, bh[nt]);
            }
        }
    }

    // ---- write out ----
#pragma unroll
    for (int sl = 0; sl < NSL; sl++) {
        float* op = out + (size_t)b * J * M + (size_t)(j0 + (s0 + sl) * 16 + gid) * M;
#pragma unroll
        for (int nt = 0; nt < NTILE; nt++) {
            const int mc = (mt0 + nt) * 8 + 2 * tq;
            *reinterpret_cast<float2*>(&op[mc]) =
                make_float2(acc[sl][nt][0], acc[sl][nt][1]);
            *reinterpret_cast<float2*>(&op[(size_t)8 * M + mc]) =
                make_float2(acc[sl][nt][2], acc[sl][nt][3]);
        }
    }
}

extern "C" void kernel_launch(void* const* d_in, const int* in_sizes, int n_in,
                              void* d_out, int out_size)
{
    const float* x   = (const float*)d_in[0];
    const float* EN3 = (const float*)d_in[1];
    const float* EN2 = (const float*)d_in[2];
    const float* EN1 = (const float*)d_in[3];
    const float* DE3 = (const float*)d_in[4];
    const float* DE2 = (const float*)d_in[5];
    const float* DE1 = (const float*)d_in[6];
    float* out = (float*)d_out;

    float *bufA, *bufB, *bufC;
    cudaGetSymbolAddress((void**)&bufA, g_bufA);
    cudaGetSymbolAddress((void**)&bufB, g_bufB);
    cudaGetSymbolAddress((void**)&bufC, g_bufC);
    float2 *wfHi, *wfLo;
    cudaGetSymbolAddress((void**)&wfHi, g_wfHi);
    cudaGetSymbolAddress((void**)&wfLo, g_wfLo);

    prep_wfrag<<<dim3(24, 6), 128>>>(EN3, EN2, EN1, DE3, DE2, DE1);

    // Encode: K=128,M=48. 4 warps = 2 m-warps (NTILE=3) x 2 j-groups (NSL=2).
    //   BJ=64, smem = 32KB fp32 (split at use), 6 blocks/SM forced.
    // Decode: K=48,M=128. 8 warps = 8 m-warps (NTILE=2), NSL=2 shared strips.
    //   BJ=32, smem = 12KB hi/lo pre-split, 4 blocks/SM forced.
    // (single decode ordering == averaged result exactly; mode contractions commute)
    auto enc = mma_stage<128, 48, 4, 4, 2, 3, false, 6>;
    auto dec = mma_stage<48, 128, 8, 2, 8, 2, true, 4>;

    // S1: contract d.  x[bc][d][hw]   (J=16384) -> bufA = [bc][h][w][p]
    enc<<<dim3(256, 1, BC), 128>>>(x,    wfHi + 0*3072, wfLo + 0*3072, bufA, 16384);
    // S2: contract h.  bufA[bc][h][wp] (J=6144) -> bufB = [bc][w][p][q]
    enc<<<dim3(96, 1, BC), 128>>>(bufA, wfHi + 1*3072, wfLo + 1*3072, bufB, 6144);
    // S3: contract w.  bufB[bc][w][pq] (J=2304) -> bufC = enc = [bc][p][q][r]
    enc<<<dim3(36, 1, BC), 128>>>(bufB, wfHi + 2*3072, wfLo + 2*3072, bufC, 2304);

    // S4: contract p.  enc[bc][p][qr]  (J=2304) -> bufB = [bc][q][r][d]
    dec<<<dim3(72, 1, BC), 256>>>(bufC, wfHi + 3*3072, wfLo + 3*3072, bufB, 2304);
    // S5: contract q.  bufB[bc][q][rd] (J=6144) -> bufA = [bc][r][d][h]
    dec<<<dim3(192, 1, BC), 256>>>(bufB, wfHi + 4*3072, wfLo + 4*3072, bufA, 6144);
    // S6: contract r.  bufA[bc][r][dh] (J=16384) -> out = [b][c][d][h][w]
    dec<<<dim3(512, 1, BC), 256>>>(bufA, wfHi + 5*3072, wfLo + 5*3072, out, 16384);
}

// round 6
// speedup vs baseline: 1.0895x; 1.0895x over previous
#include <cuda_runtime.h>
#include <cstdint>

// Problem constants: B*C = 16, L = 128, N = 48
#define BC 16

// Scratch (device globals; allocation in kernel_launch is forbidden)
__device__ float g_bufA[(size_t)BC * 16384 * 48];
__device__ float g_bufB[(size_t)BC * 6144  * 48];
__device__ float g_bufC[(size_t)BC * 2304  * 48];

// Precomputed W fragments (mma B-operand layout), hi/lo tf32 split.
__device__ float2 g_wfHi[6][3072];
__device__ float2 g_wfLo[6][3072];

__device__ __forceinline__ float tf32r(float v) {
    uint32_t r; asm("cvt.rna.tf32.f32 %0, %1;" : "=r"(r) : "f"(v));
    return __uint_as_float(r);
}

__device__ __forceinline__ void mma_tf32(float d[4], const float4& a, const float2& b) {
    asm volatile(
        "mma.sync.aligned.m16n8k8.row.col.f32.tf32.tf32.f32 "
        "{%0,%1,%2,%3}, {%4,%5,%6,%7}, {%8,%9}, {%0,%1,%2,%3};"
        : "+f"(d[0]), "+f"(d[1]), "+f"(d[2]), "+f"(d[3])
        : "r"(__float_as_uint(a.x)), "r"(__float_as_uint(a.y)),
          "r"(__float_as_uint(a.z)), "r"(__float_as_uint(a.w)),
          "r"(__float_as_uint(b.x)), "r"(__float_as_uint(b.y)));
}

// Build mma-B-fragment layout for all 6 weight matrices (hi/lo tf32 split).
__global__ void prep_wfrag(const float* __restrict__ W0, const float* __restrict__ W1,
                           const float* __restrict__ W2, const float* __restrict__ W3,
                           const float* __restrict__ W4, const float* __restrict__ W5)
{
    const int m = blockIdx.y;
    const float* W = (m==0)?W0:(m==1)?W1:(m==2)?W2:(m==3)?W3:(m==4)?W4:W5;
    const int M   = (m < 3) ? 48 : 128;
    const int NMT = M / 8;
    const int t = blockIdx.x * blockDim.x + threadIdx.x;   // 0..3071
    const int rem  = t % (NMT * 32);
    const int kc   = t / (NMT * 32);
    const int mt   = rem / 32;
    const int lane = rem % 32;
    const int tq = lane & 3, gid = lane >> 2;
    const float v0 = W[(kc*8 + tq)     * M + mt*8 + gid];
    const float v1 = W[(kc*8 + tq + 4) * M + mt*8 + gid];
    const float h0 = tf32r(v0), h1 = tf32r(v1);
    g_wfHi[m][t] = make_float2(h0, h1);
    g_wfLo[m][t] = make_float2(tf32r(v0 - h0), tf32r(v1 - h1));
}

// out[b][j][m] = sum_k in[b][k][j] * W[k][m]   (3xTF32, m16n8k8)
// MWARPS m-warps x JW j-groups; each warp: NSL strips x NTILE 8-wide m-tiles.
// A panel staged once in smem, fragment-ready (one LDS.128 = one fragment).
// PRESPLIT=false: smem holds fp32, hi/lo split in regs at use (encode).
// PRESPLIT=true:  smem holds hi/lo pre-split (decode).
// kc-outer loop with double-buffered B-fragment LDGs (prefetch next kc).
template<int K, int M, int NW, int NS, int MWARPS, int NTILE, bool PRESPLIT, int MINB>
__global__ void __launch_bounds__(NW * 32, MINB) mma_stage(
    const float* __restrict__ in, const float2* __restrict__ wHi,
    const float2* __restrict__ wLo, float* __restrict__ out, int J)
{
    constexpr int KC  = K / 8;
    constexpr int NMT = M / 8;
    constexpr int BJ  = NS * 16;
    constexpr int JW  = NW / MWARPS;
    constexpr int NSL = NS / JW;

    __shared__ float4 As[(PRESPLIT ? 2 : 1) * KC * NS * 32];

    const int tid  = threadIdx.x;
    const int lane = tid & 31, warp = tid >> 5;
    const int tq = lane & 3, gid = lane >> 2;
    const int b  = blockIdx.z;
    const int j0 = blockIdx.x * BJ;
    const int mt0 = (warp % MWARPS) * NTILE;
    const int s0  = (warp / MWARPS) * NSL;

    // ---- stage A panel (lane-owns-slot fragment layout) ----
    const float* inb = in + (size_t)b * K * J + j0;
#pragma unroll
    for (int t = warp; t < KC * NS; t += NW) {
        const int kcb = t / NS, s = t % NS;
        const float* p = inb + (size_t)(kcb * 8 + tq) * J + s * 16 + gid;
        float4 v = make_float4(__ldg(p), __ldg(p + 8),
                               __ldg(p + (size_t)4 * J), __ldg(p + (size_t)4 * J + 8));
        if (PRESPLIT) {
            float4 h = make_float4(tf32r(v.x), tf32r(v.y), tf32r(v.z), tf32r(v.w));
            float4 l = make_float4(tf32r(v.x - h.x), tf32r(v.y - h.y),
                                   tf32r(v.z - h.z), tf32r(v.w - h.w));
            As[t * 32 + lane] = h;
            As[KC * NS * 32 + t * 32 + lane] = l;
        } else {
            As[t * 32 + lane] = v;
        }
    }
    __syncthreads();

    float acc[NSL][NTILE][4];
#pragma unroll
    for (int sl = 0; sl < NSL; sl++)
#pragma unroll
        for (int nt = 0; nt < NTILE; nt++)
#pragma unroll
            for (int r = 0; r < 4; r++) acc[sl][nt][r] = 0.0f;

    // ---- kc loop, double-buffered B fragments ----
    float2 bh[2][NTILE], bl[2][NTILE];
#pragma unroll
    for (int nt = 0; nt < NTILE; nt++) {
        bh[0][nt] = __ldg(&wHi[(0 * NMT + mt0 + nt) * 32 + lane]);
        bl[0][nt] = __ldg(&wLo[(0 * NMT + mt0 + nt) * 32 + lane]);
    }

#pragma unroll
    for (int kc = 0; kc < KC; kc++) {
        const int cur = kc & 1, nxt = cur ^ 1;
        if (kc + 1 < KC) {
#pragma unroll
            for (int nt = 0; nt < NTILE; nt++) {
                bh[nxt][nt] = __ldg(&wHi[((kc + 1) * NMT + mt0 + nt) * 32 + lane]);
                bl[nxt][nt] = __ldg(&wLo[((kc + 1) * NMT + mt0 + nt) * 32 + lane]);
            }
        }
#pragma unroll
        for (int sl = 0; sl < NSL; sl++) {
            float4 ah, al;
            if (PRESPLIT) {
                ah = As[(kc * NS + s0 + sl) * 32 + lane];
                al = As[KC * NS * 32 + (kc * NS + s0 + sl) * 32 + lane];
            } else {
                float4 v = As[(kc * NS + s0 + sl) * 32 + lane];
                ah = make_float4(tf32r(v.x), tf32r(v.y), tf32r(v.z), tf32r(v.w));
                al = make_float4(tf32r(v.x - ah.x), tf32r(v.y - ah.y),
                                 tf32r(v.z - ah.z), tf32r(v.w - ah.w));
            }
#pragma unroll
            for (int nt = 0; nt < NTILE; nt++) {
                mma_tf32(acc[sl][nt], al, bh[cur][nt]);   // small cross terms first
                mma_tf32(acc[sl][nt], ah, bl[cur][nt]);
                mma_tf32(acc[sl][nt], ah, bh[cur][nt]);
            }
        }
    }

    // ---- write out ----
#pragma unroll
    for (int sl = 0; sl < NSL; sl++) {
        float* op = out + (size_t)b * J * M + (size_t)(j0 + (s0 + sl) * 16 + gid) * M;
#pragma unroll
        for (int nt = 0; nt < NTILE; nt++) {
            const int mc = (mt0 + nt) * 8 + 2 * tq;
            *reinterpret_cast<float2*>(&op[mc]) =
                make_float2(acc[sl][nt][0], acc[sl][nt][1]);
            *reinterpret_cast<float2*>(&op[(size_t)8 * M + mc]) =
                make_float2(acc[sl][nt][2], acc[sl][nt][3]);
        }
    }
}

extern "C" void kernel_launch(void* const* d_in, const int* in_sizes, int n_in,
                              void* d_out, int out_size)
{
    const float* x   = (const float*)d_in[0];
    const float* EN3 = (const float*)d_in[1];
    const float* EN2 = (const float*)d_in[2];
    const float* EN1 = (const float*)d_in[3];
    const float* DE3 = (const float*)d_in[4];
    const float* DE2 = (const float*)d_in[5];
    const float* DE1 = (const float*)d_in[6];
    float* out = (float*)d_out;

    float *bufA, *bufB, *bufC;
    cudaGetSymbolAddress((void**)&bufA, g_bufA);
    cudaGetSymbolAddress((void**)&bufB, g_bufB);
    cudaGetSymbolAddress((void**)&bufC, g_bufC);
    float2 *wfHi, *wfLo;
    cudaGetSymbolAddress((void**)&wfHi, g_wfHi);
    cudaGetSymbolAddress((void**)&wfLo, g_wfLo);

    prep_wfrag<<<dim3(24, 6), 128>>>(EN3, EN2, EN1, DE3, DE2, DE1);

    // Encode: K=128,M=48. 4 warps = 2 m-warps(NTILE=3) x 2 j-groups(NSL=1).
    //   BJ=32, smem 16KB fp32 (split at use), minB=8 -> 32 warps/SM.
    // Decode: K=48,M=128. 8 warps = 8 m-warps(NTILE=2), NSL=2 shared strips.
    //   BJ=32, smem 12KB pre-split hi/lo, minB=4 -> 32 warps/SM.
    // (single decode ordering == averaged result exactly; mode contractions commute)
    auto enc = mma_stage<128, 48, 4, 2, 2, 3, false, 8>;
    auto dec = mma_stage<48, 128, 8, 2, 8, 2, true, 4>;

    // S1: contract d.  x[bc][d][hw]   (J=16384) -> bufA = [bc][h][w][p]
    enc<<<dim3(512, 1, BC), 128>>>(x,    wfHi + 0*3072, wfLo + 0*3072, bufA, 16384);
    // S2: contract h.  bufA[bc][h][wp] (J=6144) -> bufB = [bc][w][p][q]
    enc<<<dim3(192, 1, BC), 128>>>(bufA, wfHi + 1*3072, wfLo + 1*3072, bufB, 6144);
    // S3: contract w.  bufB[bc][w][pq] (J=2304) -> bufC = enc = [bc][p][q][r]
    enc<<<dim3(72, 1, BC), 128>>>(bufB, wfHi + 2*3072, wfLo + 2*3072, bufC, 2304);

    // S4: contract p.  enc[bc][p][qr]  (J=2304) -> bufB = [bc][q][r][d]
    dec<<<dim3(72, 1, BC), 256>>>(bufC, wfHi + 3*3072, wfLo + 3*3072, bufB, 2304);
    // S5: contract q.  bufB[bc][q][rd] (J=6144) -> bufA = [bc][r][d][h]
    dec<<<dim3(192, 1, BC), 256>>>(bufB, wfHi + 4*3072, wfLo + 4*3072, bufA, 6144);
    // S6: contract r.  bufA[bc][r][dh] (J=16384) -> out = [b][c][d][h][w]
    dec<<<dim3(512, 1, BC), 256>>>(bufA, wfHi + 5*3072, wfLo + 5*3072, out, 16384);
}

// round 7
// speedup vs baseline: 1.3761x; 1.2631x over previous
#include <cuda_runtime.h>
#include <cuda_bf16.h>
#include <cstdint>

// Problem constants: B*C = 16, L = 128, N = 48
#define BC 16

// Scratch (device globals; allocation in kernel_launch is forbidden)
__device__ float g_bufA[(size_t)BC * 16384 * 48];
__device__ float g_bufB[(size_t)BC * 6144  * 48];
__device__ float g_bufC[(size_t)BC * 2304  * 48];

// Precomputed W fragments (mma.m16n8k16 B-operand layout), bf16 hi/lo split.
// Per matrix: KC16 * NMT * 32 lane-slots = 1536 uint2 (both enc 8*6*32 and dec 3*16*32).
__device__ uint2 g_wfHi[6][1536];
__device__ uint2 g_wfLo[6][1536];

__device__ __forceinline__ float bf16hi(float v) {
    return __bfloat162float(__float2bfloat16_rn(v));
}
__device__ __forceinline__ uint32_t packbf2(float a, float b) {
    __nv_bfloat162 t = __floats2bfloat162_rn(a, b);   // x=a (low), y=b (high)
    return *reinterpret_cast<uint32_t*>(&t);
}

__device__ __forceinline__ void mma_bf16(float d[4], const uint4& a, const uint2& b) {
    asm volatile(
        "mma.sync.aligned.m16n8k16.row.col.f32.bf16.bf16.f32 "
        "{%0,%1,%2,%3}, {%4,%5,%6,%7}, {%8,%9}, {%0,%1,%2,%3};"
        : "+f"(d[0]), "+f"(d[1]), "+f"(d[2]), "+f"(d[3])
        : "r"(a.x), "r"(a.y), "r"(a.z), "r"(a.w), "r"(b.x), "r"(b.y));
}

// Build m16n8k16 B-fragment layout for all 6 weight matrices (bf16 hi/lo split).
// b0 = {W[k0][c], W[k0+1][c]}, b1 = {W[k0+8][c], W[k0+9][c]}, k0=kc*16+2tq, c=mt*8+gid.
__global__ void prep_wfrag(const float* __restrict__ W0, const float* __restrict__ W1,
                           const float* __restrict__ W2, const float* __restrict__ W3,
                           const float* __restrict__ W4, const float* __restrict__ W5)
{
    const int m = blockIdx.y;
    const float* W = (m==0)?W0:(m==1)?W1:(m==2)?W2:(m==3)?W3:(m==4)?W4:W5;
    const int M   = (m < 3) ? 48 : 128;
    const int NMT = M / 8;
    const int t = blockIdx.x * blockDim.x + threadIdx.x;   // 0..1535
    const int rem  = t % (NMT * 32);
    const int kc   = t / (NMT * 32);
    const int mt   = rem / 32;
    const int lane = rem % 32;
    const int tq = lane & 3, gid = lane >> 2;
    const int k0 = kc * 16 + 2 * tq;
    const int c  = mt * 8 + gid;
    const float w00 = W[(k0    ) * M + c], w01 = W[(k0 + 1) * M + c];
    const float w08 = W[(k0 + 8) * M + c], w09 = W[(k0 + 9) * M + c];
    const float h00 = bf16hi(w00), h01 = bf16hi(w01);
    const float h08 = bf16hi(w08), h09 = bf16hi(w09);
    g_wfHi[m][t] = make_uint2(packbf2(h00, h01), packbf2(h08, h09));
    g_wfLo[m][t] = make_uint2(packbf2(w00 - h00, w01 - h01), packbf2(w08 - h08, w09 - h09));
}

// out[b][j][m] = sum_k in[b][k][j] * W[k][m]   (bf16 2-split, 3 products, m16n8k16)
// MWARPS m-warps x JW j-groups; each warp: NSL strips x NTILE 8-wide m-tiles.
// A panel staged once in smem, fragment-ready bf16 hi/lo (one LDS.128 = one frag).
// kc-outer loop, B fragments double-buffered in regs, reused across NSL strips.
template<int K, int M, int NW, int NS, int MWARPS, int NTILE, int MINB>
__global__ void __launch_bounds__(NW * 32, MINB) mma_stage(
    const float* __restrict__ in, const uint2* __restrict__ wHi,
    const uint2* __restrict__ wLo, float* __restrict__ out, int J)
{
    constexpr int KC  = K / 16;
    constexpr int NMT = M / 8;
    constexpr int BJ  = NS * 16;
    constexpr int JW  = NW / MWARPS;
    constexpr int NSL = NS / JW;

    __shared__ uint4 AsH[KC * NS * 32];
    __shared__ uint4 AsL[KC * NS * 32];

    const int tid  = threadIdx.x;
    const int lane = tid & 31, warp = tid >> 5;
    const int tq = lane & 3, gid = lane >> 2;
    const int b  = blockIdx.z;
    const int j0 = blockIdx.x * BJ;
    const int mt0 = (warp % MWARPS) * NTILE;
    const int s0  = (warp / MWARPS) * NSL;

    // ---- stage A panel: lane-owns-slot, bf16 hi/lo fragment layout ----
    // A frag (m16n8k16): a0={A[gid][k0],A[gid][k0+1]} a1=row gid+8, a2/a3 = k0+8,k0+9.
    const float* inb = in + (size_t)b * K * J + j0;
#pragma unroll
    for (int t = warp; t < KC * NS; t += NW) {
        const int kcb = t / NS, s = t % NS;
        const float* p = inb + (size_t)(kcb * 16 + 2 * tq) * J + s * 16 + gid;
        const float x00 = __ldg(p),                    y00 = __ldg(p + 8);
        const float x01 = __ldg(p + (size_t)J),        y01 = __ldg(p + (size_t)J + 8);
        const float x08 = __ldg(p + (size_t)8 * J),    y08 = __ldg(p + (size_t)8 * J + 8);
        const float x09 = __ldg(p + (size_t)9 * J),    y09 = __ldg(p + (size_t)9 * J + 8);
        const float hx00 = bf16hi(x00), hx01 = bf16hi(x01), hx08 = bf16hi(x08), hx09 = bf16hi(x09);
        const float hy00 = bf16hi(y00), hy01 = bf16hi(y01), hy08 = bf16hi(y08), hy09 = bf16hi(y09);
        AsH[t * 32 + lane] = make_uint4(packbf2(hx00, hx01), packbf2(hy00, hy01),
                                        packbf2(hx08, hx09), packbf2(hy08, hy09));
        AsL[t * 32 + lane] = make_uint4(packbf2(x00 - hx00, x01 - hx01),
                                        packbf2(y00 - hy00, y01 - hy01),
                                        packbf2(x08 - hx08, x09 - hx09),
                                        packbf2(y08 - hy08, y09 - hy09));
    }
    __syncthreads();

    float acc[NSL][NTILE][4];
#pragma unroll
    for (int sl = 0; sl < NSL; sl++)
#pragma unroll
        for (int nt = 0; nt < NTILE; nt++)
#pragma unroll
            for (int r = 0; r < 4; r++) acc[sl][nt][r] = 0.0f;

    // ---- kc loop, double-buffered B fragments ----
    uint2 bh[2][NTILE], bl[2][NTILE];
#pragma unroll
    for (int nt = 0; nt < NTILE; nt++) {
        bh[0][nt] = __ldg(&wHi[(mt0 + nt) * 32 + lane]);
        bl[0][nt] = __ldg(&wLo[(mt0 + nt) * 32 + lane]);
    }

#pragma unroll
    for (int kc = 0; kc < KC; kc++) {
        const int cur = kc & 1, nxt = cur ^ 1;
        if (kc + 1 < KC) {
#pragma unroll
            for (int nt = 0; nt < NTILE; nt++) {
                bh[nxt][nt] = __ldg(&wHi[((kc + 1) * NMT + mt0 + nt) * 32 + lane]);
                bl[nxt][nt] = __ldg(&wLo[((kc + 1) * NMT + mt0 + nt) * 32 + lane]);
            }
        }
#pragma unroll
        for (int sl = 0; sl < NSL; sl++) {
            const uint4 ah = AsH[(kc * NS + s0 + sl) * 32 + lane];
            const uint4 al = AsL[(kc * NS + s0 + sl) * 32 + lane];
#pragma unroll
            for (int nt = 0; nt < NTILE; nt++) {
                mma_bf16(acc[sl][nt], al, bh[cur][nt]);   // small terms first
                mma_bf16(acc[sl][nt], ah, bl[cur][nt]);
                mma_bf16(acc[sl][nt], ah, bh[cur][nt]);
            }
        }
    }

    // ---- write out ----
#pragma unroll
    for (int sl = 0; sl < NSL; sl++) {
        float* op = out + (size_t)b * J * M + (size_t)(j0 + (s0 + sl) * 16 + gid) * M;
#pragma unroll
        for (int nt = 0; nt < NTILE; nt++) {
            const int mc = (mt0 + nt) * 8 + 2 * tq;
            *reinterpret_cast<float2*>(&op[mc]) =
                make_float2(acc[sl][nt][0], acc[sl][nt][1]);
            *reinterpret_cast<float2*>(&op[(size_t)8 * M + mc]) =
                make_float2(acc[sl][nt][2], acc[sl][nt][3]);
        }
    }
}

extern "C" void kernel_launch(void* const* d_in, const int* in_sizes, int n_in,
                              void* d_out, int out_size)
{
    const float* x   = (const float*)d_in[0];
    const float* EN3 = (const float*)d_in[1];
    const float* EN2 = (const float*)d_in[2];
    const float* EN1 = (const float*)d_in[3];
    const float* DE3 = (const float*)d_in[4];
    const float* DE2 = (const float*)d_in[5];
    const float* DE1 = (const float*)d_in[6];
    float* out = (float*)d_out;

    float *bufA, *bufB, *bufC;
    cudaGetSymbolAddress((void**)&bufA, g_bufA);
    cudaGetSymbolAddress((void**)&bufB, g_bufB);
    cudaGetSymbolAddress((void**)&bufC, g_bufC);
    uint2 *wfHi, *wfLo;
    cudaGetSymbolAddress((void**)&wfHi, g_wfHi);
    cudaGetSymbolAddress((void**)&wfLo, g_wfLo);

    prep_wfrag<<<dim3(12, 6), 128>>>(EN3, EN2, EN1, DE3, DE2, DE1);

    // Encode: K=128,M=48. 2 warps = 2 m-warps (NTILE=3), JW=1, NSL=2. BJ=32.
    //   smem 16KB bf16 hi/lo, 64-thr blocks, ~12 blocks/SM.
    // Decode: K=48,M=128. 8 warps = 8 m-warps (NTILE=2), JW=1, NSL=2. BJ=32.
    //   smem 6KB, 256-thr blocks, minB=4 -> 32 warps/SM.
    // (single decode ordering == averaged result exactly; mode contractions commute)
    auto enc = mma_stage<128, 48, 2, 2, 2, 3, 12>;
    auto dec = mma_stage<48, 128, 8, 2, 8, 2, 4>;

    // S1: contract d.  x[bc][d][hw]   (J=16384) -> bufA = [bc][h][w][p]
    enc<<<dim3(512, 1, BC), 64>>>(x,    wfHi + 0*1536, wfLo + 0*1536, bufA, 16384);
    // S2: contract h.  bufA[bc][h][wp] (J=6144) -> bufB = [bc][w][p][q]
    enc<<<dim3(192, 1, BC), 64>>>(bufA, wfHi + 1*1536, wfLo + 1*1536, bufB, 6144);
    // S3: contract w.  bufB[bc][w][pq] (J=2304) -> bufC = enc = [bc][p][q][r]
    enc<<<dim3(72, 1, BC), 64>>>(bufB, wfHi + 2*1536, wfLo + 2*1536, bufC, 2304);

    // S4: contract p.  enc[bc][p][qr]  (J=2304) -> bufB = [bc][q][r][d]
    dec<<<dim3(72, 1, BC), 256>>>(bufC, wfHi + 3*1536, wfLo + 3*1536, bufB, 2304);
    // S5: contract q.  bufB[bc][q][rd] (J=6144) -> bufA = [bc][r][d][h]
    dec<<<dim3(192, 1, BC), 256>>>(bufB, wfHi + 4*1536, wfLo + 4*1536, bufA, 6144);
    // S6: contract r.  bufA[bc][r][dh] (J=16384) -> out = [b][c][d][h][w]
    dec<<<dim3(512, 1, BC), 256>>>(bufA, wfHi + 5*1536, wfLo + 5*1536, out, 16384);
}

// round 8
// speedup vs baseline: 1.3840x; 1.0058x over previous
#include <cuda_runtime.h>
#include <cuda_bf16.h>
#include <cstdint>

// Problem constants: B*C = 16, L = 128, N = 48
#define BC 16

// Scratch (device globals; allocation in kernel_launch is forbidden)
__device__ float g_bufA[(size_t)BC * 16384 * 48];
__device__ float g_bufB[(size_t)BC * 6144  * 48];
__device__ float g_bufC[(size_t)BC * 2304  * 48];

// Precomputed W fragments (mma.m16n8k16 B-operand layout), bf16 hi/lo split.
__device__ uint2 g_wfHi[6][1536];
__device__ uint2 g_wfLo[6][1536];

__device__ __forceinline__ float bf16hi(float v) {
    return __bfloat162float(__float2bfloat16_rn(v));
}
__device__ __forceinline__ uint32_t packbf2(float a, float b) {
    __nv_bfloat162 t = __floats2bfloat162_rn(a, b);
    return *reinterpret_cast<uint32_t*>(&t);
}

__device__ __forceinline__ void mma_bf16(float d[4], const uint4& a, const uint2& b) {
    asm volatile(
        "mma.sync.aligned.m16n8k16.row.col.f32.bf16.bf16.f32 "
        "{%0,%1,%2,%3}, {%4,%5,%6,%7}, {%8,%9}, {%0,%1,%2,%3};"
        : "+f"(d[0]), "+f"(d[1]), "+f"(d[2]), "+f"(d[3])
        : "r"(a.x), "r"(a.y), "r"(a.z), "r"(a.w), "r"(b.x), "r"(b.y));
}

// Build m16n8k16 B-fragment layout for all 6 weight matrices (bf16 hi/lo split).
__global__ void prep_wfrag(const float* __restrict__ W0, const float* __restrict__ W1,
                           const float* __restrict__ W2, const float* __restrict__ W3,
                           const float* __restrict__ W4, const float* __restrict__ W5)
{
    const int m = blockIdx.y;
    const float* W = (m==0)?W0:(m==1)?W1:(m==2)?W2:(m==3)?W3:(m==4)?W4:W5;
    const int M   = (m < 3) ? 48 : 128;
    const int NMT = M / 8;
    const int t = blockIdx.x * blockDim.x + threadIdx.x;   // 0..1535
    const int rem  = t % (NMT * 32);
    const int kc   = t / (NMT * 32);
    const int mt   = rem / 32;
    const int lane = rem % 32;
    const int tq = lane & 3, gid = lane >> 2;
    const int k0 = kc * 16 + 2 * tq;
    const int c  = mt * 8 + gid;
    const float w00 = W[(k0    ) * M + c], w01 = W[(k0 + 1) * M + c];
    const float w08 = W[(k0 + 8) * M + c], w09 = W[(k0 + 9) * M + c];
    const float h00 = bf16hi(w00), h01 = bf16hi(w01);
    const float h08 = bf16hi(w08), h09 = bf16hi(w09);
    g_wfHi[m][t] = make_uint2(packbf2(h00, h01), packbf2(h08, h09));
    g_wfLo[m][t] = make_uint2(packbf2(w00 - h00, w01 - h01), packbf2(w08 - h08, w09 - h09));
}

// out[b][j][m] = sum_k in[b][k][j] * W[k][m]   (bf16 2-split, 3 products, m16n8k16)
// MWARPS m-warps x JW j-groups; each warp: NSL strips x NTILE 8-wide m-tiles.
// A panel staged once in smem, fragment-ready bf16 hi/lo (one LDS.128 = one frag).
// kc-outer loop, B fragments double-buffered in regs.
template<int K, int M, int NW, int NS, int MWARPS, int NTILE, int MINB>
__global__ void __launch_bounds__(NW * 32, MINB) mma_stage(
    const float* __restrict__ in, const uint2* __restrict__ wHi,
    const uint2* __restrict__ wLo, float* __restrict__ out, int J)
{
    constexpr int KC  = K / 16;
    constexpr int NMT = M / 8;
    constexpr int BJ  = NS * 16;
    constexpr int JW  = NW / MWARPS;
    constexpr int NSL = NS / JW;

    __shared__ uint4 AsH[KC * NS * 32];
    __shared__ uint4 AsL[KC * NS * 32];

    const int tid  = threadIdx.x;
    const int lane = tid & 31, warp = tid >> 5;
    const int tq = lane & 3, gid = lane >> 2;
    const int b  = blockIdx.z;
    const int j0 = blockIdx.x * BJ;
    const int mt0 = (warp % MWARPS) * NTILE;
    const int s0  = (warp / MWARPS) * NSL;

    // ---- stage A panel: lane-owns-slot, bf16 hi/lo fragment layout ----
    const float* inb = in + (size_t)b * K * J + j0;
#pragma unroll
    for (int t = warp; t < KC * NS; t += NW) {
        const int kcb = t / NS, s = t % NS;
        const float* p = inb + (size_t)(kcb * 16 + 2 * tq) * J + s * 16 + gid;
        const float x00 = __ldg(p),                    y00 = __ldg(p + 8);
        const float x01 = __ldg(p + (size_t)J),        y01 = __ldg(p + (size_t)J + 8);
        const float x08 = __ldg(p + (size_t)8 * J),    y08 = __ldg(p + (size_t)8 * J + 8);
        const float x09 = __ldg(p + (size_t)9 * J),    y09 = __ldg(p + (size_t)9 * J + 8);
        const float hx00 = bf16hi(x00), hx01 = bf16hi(x01), hx08 = bf16hi(x08), hx09 = bf16hi(x09);
        const float hy00 = bf16hi(y00), hy01 = bf16hi(y01), hy08 = bf16hi(y08), hy09 = bf16hi(y09);
        AsH[t * 32 + lane] = make_uint4(packbf2(hx00, hx01), packbf2(hy00, hy01),
                                        packbf2(hx08, hx09), packbf2(hy08, hy09));
        AsL[t * 32 + lane] = make_uint4(packbf2(x00 - hx00, x01 - hx01),
                                        packbf2(y00 - hy00, y01 - hy01),
                                        packbf2(x08 - hx08, x09 - hx09),
                                        packbf2(y08 - hy08, y09 - hy09));
    }
    __syncthreads();

    float acc[NSL][NTILE][4];
#pragma unroll
    for (int sl = 0; sl < NSL; sl++)
#pragma unroll
        for (int nt = 0; nt < NTILE; nt++)
#pragma unroll
            for (int r = 0; r < 4; r++) acc[sl][nt][r] = 0.0f;

    // ---- kc loop, double-buffered B fragments ----
    uint2 bh[2][NTILE], bl[2][NTILE];
#pragma unroll
    for (int nt = 0; nt < NTILE; nt++) {
        bh[0][nt] = __ldg(&wHi[(mt0 + nt) * 32 + lane]);
        bl[0][nt] = __ldg(&wLo[(mt0 + nt) * 32 + lane]);
    }

#pragma unroll
    for (int kc = 0; kc < KC; kc++) {
        const int cur = kc & 1, nxt = cur ^ 1;
        if (kc + 1 < KC) {
#pragma unroll
            for (int nt = 0; nt < NTILE; nt++) {
                bh[nxt][nt] = __ldg(&wHi[((kc + 1) * NMT + mt0 + nt) * 32 + lane]);
                bl[nxt][nt] = __ldg(&wLo[((kc + 1) * NMT + mt0 + nt) * 32 + lane]);
            }
        }
#pragma unroll
        for (int sl = 0; sl < NSL; sl++) {
            const uint4 ah = AsH[(kc * NS + s0 + sl) * 32 + lane];
            const uint4 al = AsL[(kc * NS + s0 + sl) * 32 + lane];
#pragma unroll
            for (int nt = 0; nt < NTILE; nt++) {
                mma_bf16(acc[sl][nt], al, bh[cur][nt]);   // small terms first
                mma_bf16(acc[sl][nt], ah, bl[cur][nt]);
                mma_bf16(acc[sl][nt], ah, bh[cur][nt]);
            }
        }
    }

    // ---- write out ----
#pragma unroll
    for (int sl = 0; sl < NSL; sl++) {
        float* op = out + (size_t)b * J * M + (size_t)(j0 + (s0 + sl) * 16 + gid) * M;
#pragma unroll
        for (int nt = 0; nt < NTILE; nt++) {
            const int mc = (mt0 + nt) * 8 + 2 * tq;
            *reinterpret_cast<float2*>(&op[mc]) =
                make_float2(acc[sl][nt][0], acc[sl][nt][1]);
            *reinterpret_cast<float2*>(&op[(size_t)8 * M + mc]) =
                make_float2(acc[sl][nt][2], acc[sl][nt][3]);
        }
    }
}

extern "C" void kernel_launch(void* const* d_in, const int* in_sizes, int n_in,
                              void* d_out, int out_size)
{
    const float* x   = (const float*)d_in[0];
    const float* EN3 = (const float*)d_in[1];
    const float* EN2 = (const float*)d_in[2];
    const float* EN1 = (const float*)d_in[3];
    const float* DE3 = (const float*)d_in[4];
    const float* DE2 = (const float*)d_in[5];
    const float* DE1 = (const float*)d_in[6];
    float* out = (float*)d_out;

    float *bufA, *bufB, *bufC;
    cudaGetSymbolAddress((void**)&bufA, g_bufA);
    cudaGetSymbolAddress((void**)&bufB, g_bufB);
    cudaGetSymbolAddress((void**)&bufC, g_bufC);
    uint2 *wfHi, *wfLo;
    cudaGetSymbolAddress((void**)&wfHi, g_wfHi);
    cudaGetSymbolAddress((void**)&wfLo, g_wfLo);

    prep_wfrag<<<dim3(12, 6), 128>>>(EN3, EN2, EN1, DE3, DE2, DE1);

    // Encode: K=128,M=48. 4 warps = 2 m-warps(NTILE=3) x 2 j-groups(NSL=1).
    //   BJ=32, smem 16KB bf16 hi/lo, 128-thr blocks, minB=8 -> 32 warps/SM.
    // Decode: K=48,M=128. 8 warps = 8 m-warps(NTILE=2), JW=1, NSL=2. BJ=32.
    //   smem 6KB, 256-thr blocks, minB=4 -> 32 warps/SM.
    // (single decode ordering == averaged result exactly; mode contractions commute)
    auto enc = mma_stage<128, 48, 4, 2, 2, 3, 8>;
    auto dec = mma_stage<48, 128, 8, 2, 8, 2, 4>;

    // S1: contract d.  x[bc][d][hw]   (J=16384) -> bufA = [bc][h][w][p]
    enc<<<dim3(512, 1, BC), 128>>>(x,    wfHi + 0*1536, wfLo + 0*1536, bufA, 16384);
    // S2: contract h.  bufA[bc][h][wp] (J=6144) -> bufB = [bc][w][p][q]
    enc<<<dim3(192, 1, BC), 128>>>(bufA, wfHi + 1*1536, wfLo + 1*1536, bufB, 6144);
    // S3: contract w.  bufB[bc][w][pq] (J=2304) -> bufC = enc = [bc][p][q][r]
    enc<<<dim3(72, 1, BC), 128>>>(bufB, wfHi + 2*1536, wfLo + 2*1536, bufC, 2304);

    // S4: contract p.  enc[bc][p][qr]  (J=2304) -> bufB = [bc][q][r][d]
    dec<<<dim3(72, 1, BC), 256>>>(bufC, wfHi + 3*1536, wfLo + 3*1536, bufB, 2304);
    // S5: contract q.  bufB[bc][q][rd] (J=6144) -> bufA = [bc][r][d][h]
    dec<<<dim3(192, 1, BC), 256>>>(bufB, wfHi + 4*1536, wfLo + 4*1536, bufA, 6144);
    // S6: contract r.  bufA[bc][r][dh] (J=16384) -> out = [b][c][d][h][w]
    dec<<<dim3(512, 1, BC), 256>>>(bufA, wfHi + 5*1536, wfLo + 5*1536, out, 16384);
}